// round 8
// baseline (speedup 1.0000x reference)
#include <cuda_runtime.h>
#include <cuda_fp16.h>

#define NPTS 500000
#define NCLS 20
#define RPAD 32      // padded row stride in halves (64 B, line-aligned)
#define NK   16

// fp16 probs table, 64B rows: 500000*32*2B = 32 MB (L2-resident). No alloc.
__device__ __half g_probs_h[(size_t)NPTS * RPAD];
__device__ float  g_acc[2];    // [0]=sum of mean_dist over valid pts, [1]=valid count
__device__ int    g_done = 0;

// Kernel 1: softmax (fp32 in, fp16 out, padded rows) + accumulator reset.
__global__ void softmax_kernel(const float* __restrict__ logits) {
    if (blockIdx.x == 0 && threadIdx.x == 0) {
        g_acc[0] = 0.0f;
        g_acc[1] = 0.0f;
        g_done   = 0;
    }
    int n = blockIdx.x * blockDim.x + threadIdx.x;
    if (n >= NPTS) return;
    const float4* src = reinterpret_cast<const float4*>(logits + (size_t)n * NCLS);
    float4 v[5];
#pragma unroll
    for (int i = 0; i < 5; i++) v[i] = src[i];
    float* f = reinterpret_cast<float*>(v);
    float m = f[0];
#pragma unroll
    for (int i = 1; i < NCLS; i++) m = fmaxf(m, f[i]);
    float s = 0.0f;
#pragma unroll
    for (int i = 0; i < NCLS; i++) { f[i] = __expf(f[i] - m); s += f[i]; }
    float inv = 1.0f / s;
    __half2* dst = reinterpret_cast<__half2*>(g_probs_h + ((size_t)n << 5));
#pragma unroll
    for (int i = 0; i < 10; i++)
        dst[i] = __floats2half2_rn(f[2 * i] * inv, f[2 * i + 1] * inv);
}

// Kernel 2: warp-per-2-points gather (MLP x2), half2 math, line-aligned rows.
// Index load uses the FULL warp: lanes 0-15 hold point0's 16 neighbor indices,
// lanes 16-31 hold point1's. One coalesced LDG + one ballot per 2 points.
// Gather lane layout: grp = lane>>3 (0..3), sub = lane&7; lanes with sub<5 own
// classes [4*sub,4*sub+4) as uint2 (two half2). Step s: group g handles
// neighbor 4*s+g -> one LDG.64 gathers 4 rows, each row in exactly 1 L1 line.
__global__ void loss_kernel(const int* __restrict__ nbr,
                            const int* __restrict__ labels,
                            float* __restrict__ out) {
    const int lane = threadIdx.x & 31;
    const int warpInBlock = threadIdx.x >> 5;
    const int warpsPerBlock = blockDim.x >> 5;
    const int gwarp = blockIdx.x * warpsPerBlock + warpInBlock;
    const int totalWarps = gridDim.x * warpsPerBlock;
    const int grp = lane >> 3;
    const int sub = lane & 7;
    const bool active = (sub < 5);
    const int laneOff = 4 * sub;

    float accTot = 0.0f;
    float cnt    = 0.0f;
    const __half2 z2 = __float2half2_rn(0.f);

    for (int n0 = gwarp; n0 < NPTS; n0 += 2 * totalWarps) {
        const int n1 = n0 + totalWarps;
        const bool has1 = (n1 < NPTS);

        // ---- front loads for both points ----
        int lab0 = labels[n0];
        int lab1 = has1 ? labels[n1] : -1;

        // Full-warp neighbor-index load: lane<16 -> point0, lane>=16 -> point1
        int myPt = (lane < 16) ? n0 : n1;
        int myIdx = -1;
        if (myPt < NPTS) myIdx = nbr[myPt * NK + (lane & 15)];

        __half2 pa0 = z2, pb0 = z2, pa1 = z2, pb1 = z2;
        if (active) {
            uint2 pw0 = *reinterpret_cast<const uint2*>(g_probs_h + (n0 << 5) + laneOff);
            pa0 = *reinterpret_cast<__half2*>(&pw0.x);
            pb0 = *reinterpret_cast<__half2*>(&pw0.y);
            if (has1) {
                uint2 pw1 = *reinterpret_cast<const uint2*>(g_probs_h + (n1 << 5) + laneOff);
                pa1 = *reinterpret_cast<__half2*>(&pw1.x);
                pb1 = *reinterpret_cast<__half2*>(&pw1.y);
            }
        }

        // One ballot covers both points
        unsigned vm = __ballot_sync(0xFFFFFFFFu, myIdx >= 0);
        int nv0 = __popc(vm & 0xFFFFu);
        int nv1 = __popc(vm >> 16);
        bool do0 = (lab0 != -1) && nv0 > 0;
        bool do1 = has1 && (lab1 != -1) && nv1 > 0;

        // ---- all 8 shuffles, then all 8 gathers in flight ----
        int q0[4], q1[4];
#pragma unroll
        for (int s = 0; s < 4; s++) {
            q0[s] = __shfl_sync(0xFFFFFFFFu, myIdx, 4 * s + grp);
            q1[s] = __shfl_sync(0xFFFFFFFFu, myIdx, 16 + 4 * s + grp);
        }

        __half2 acc0 = z2, acc1 = z2;
#pragma unroll
        for (int s = 0; s < 4; s++) {
            if (do0 && active && q0[s] >= 0) {
                uint2 qw = *reinterpret_cast<const uint2*>(
                    g_probs_h + (q0[s] << 5) + laneOff);
                __half2 da = __hsub2(pa0, *reinterpret_cast<__half2*>(&qw.x));
                __half2 db = __hsub2(pb0, *reinterpret_cast<__half2*>(&qw.y));
                acc0 = __hfma2(da, da, acc0);
                acc0 = __hfma2(db, db, acc0);
            }
            if (do1 && active && q1[s] >= 0) {
                uint2 qw = *reinterpret_cast<const uint2*>(
                    g_probs_h + (q1[s] << 5) + laneOff);
                __half2 da = __hsub2(pa1, *reinterpret_cast<__half2*>(&qw.x));
                __half2 db = __hsub2(pb1, *reinterpret_cast<__half2*>(&qw.y));
                acc1 = __hfma2(da, da, acc1);
                acc1 = __hfma2(db, db, acc1);
            }
        }

        if (do0) {
            float2 af = __half22float2(acc0);
            accTot = fmaf(af.x + af.y, __frcp_rn((float)nv0), accTot);
        }
        if (do1) {
            float2 af = __half22float2(acc1);
            accTot = fmaf(af.x + af.y, __frcp_rn((float)nv1), accTot);
        }
        cnt += (lab0 != -1 ? 1.0f : 0.0f) + (has1 && lab1 != -1 ? 1.0f : 0.0f);
    }

    // One butterfly reduce per warp
#pragma unroll
    for (int o = 16; o > 0; o >>= 1)
        accTot += __shfl_xor_sync(0xFFFFFFFFu, accTot, o);

    // Block reduce -> one atomic pair per block
    __shared__ float sSum[32];
    __shared__ float sCnt[32];
    if (lane == 0) { sSum[warpInBlock] = accTot; sCnt[warpInBlock] = cnt; }
    __syncthreads();
    if (threadIdx.x == 0) {
        float bs = 0.0f, bc = 0.0f;
        for (int w = 0; w < warpsPerBlock; w++) { bs += sSum[w]; bc += sCnt[w]; }
        atomicAdd(&g_acc[0], bs);
        atomicAdd(&g_acc[1], bc);
        __threadfence();
        int t = atomicAdd(&g_done, 1);
        if (t == gridDim.x - 1) {
            out[0] = g_acc[0] / fmaxf(g_acc[1], 1.0f);  // LOSS_WEIGHT = 1.0
            g_done = 0;
        }
    }
}

extern "C" void kernel_launch(void* const* d_in, const int* in_sizes, int n_in,
                              void* d_out, int out_size) {
    const float* logits = nullptr;
    const int*   nbr    = nullptr;
    const int*   labels = nullptr;
    for (int i = 0; i < n_in; i++) {
        if (in_sizes[i] == NPTS * NCLS)    logits = (const float*)d_in[i];
        else if (in_sizes[i] == NPTS * NK) nbr    = (const int*)d_in[i];
        else if (in_sizes[i] == NPTS)      labels = (const int*)d_in[i];
    }
    float* out = (float*)d_out;

    softmax_kernel<<<(NPTS + 255) / 256, 256>>>(logits);
    loss_kernel<<<2048, 256>>>(nbr, labels, out);
}

// round 9
// speedup vs baseline: 1.0367x; 1.0367x over previous
#include <cuda_runtime.h>
#include <cuda_fp16.h>

#define NPTS 500000
#define NCLS 20
#define NK   16

// fp16 probs table: 500000*20*2B = 20 MB (L2-resident). Device globals (no alloc).
__device__ __half g_probs_h[(size_t)NPTS * NCLS];
__device__ float  g_acc[2];    // [0]=sum of mean_dist over valid pts, [1]=valid count
__device__ int    g_done = 0;

// Kernel 1: softmax (fp32 in, fp16 out) + accumulator reset.
__global__ void softmax_kernel(const float* __restrict__ logits) {
    if (blockIdx.x == 0 && threadIdx.x == 0) {
        g_acc[0] = 0.0f;
        g_acc[1] = 0.0f;
        g_done   = 0;
    }
    int n = blockIdx.x * blockDim.x + threadIdx.x;
    if (n >= NPTS) return;
    const float4* src = reinterpret_cast<const float4*>(logits + (size_t)n * NCLS);
    float4 v[5];
#pragma unroll
    for (int i = 0; i < 5; i++) v[i] = src[i];
    float* f = reinterpret_cast<float*>(v);
    float m = f[0];
#pragma unroll
    for (int i = 1; i < NCLS; i++) m = fmaxf(m, f[i]);
    float s = 0.0f;
#pragma unroll
    for (int i = 0; i < NCLS; i++) { f[i] = __expf(f[i] - m); s += f[i]; }
    float inv = 1.0f / s;
    __half2* dst = reinterpret_cast<__half2*>(g_probs_h + (size_t)n * NCLS);
#pragma unroll
    for (int i = 0; i < 10; i++)
        dst[i] = __floats2half2_rn(f[2 * i] * inv, f[2 * i + 1] * inv);
}

// Kernel 2: warp-per-2-points gather (MLP x2), half2 math, with one-iteration
// software prefetch of labels + neighbor indices (hides the front LDG chain).
// Index layout: lanes 0-15 hold point0's 16 neighbor indices, lanes 16-31 point1's.
// Gather lane layout: grp = lane>>3 (0..3), sub = lane&7; lanes with sub<5 own
// classes [4*sub,4*sub+4) as uint2 (two half2). Step s: group g handles
// neighbor 4*s+g -> one LDG.64 instruction gathers 4 neighbor rows.
__global__ void loss_kernel(const int* __restrict__ nbr,
                            const int* __restrict__ labels,
                            float* __restrict__ out) {
    const int lane = threadIdx.x & 31;
    const int warpInBlock = threadIdx.x >> 5;
    const int warpsPerBlock = blockDim.x >> 5;
    const int gwarp = blockIdx.x * warpsPerBlock + warpInBlock;
    const int totalWarps = gridDim.x * warpsPerBlock;
    const int step = 2 * totalWarps;
    const int grp = lane >> 3;
    const int sub = lane & 7;
    const bool active = (sub < 5);
    const int laneOff = 4 * sub;

    float accTot = 0.0f;
    float cnt    = 0.0f;
    const __half2 z2 = __float2half2_rn(0.f);

    // ---- prologue: load iteration 0's labels + indices ----
    int curLab0 = -1, curLab1 = -1, curIdx = -1;
    if (gwarp < NPTS) {
        curLab0 = labels[gwarp];
        int n1 = gwarp + totalWarps;
        curLab1 = (n1 < NPTS) ? labels[n1] : -1;
        int myPt = (lane < 16) ? gwarp : n1;
        if (myPt < NPTS) curIdx = nbr[myPt * NK + (lane & 15)];
    }

    for (int n0 = gwarp; n0 < NPTS; n0 += step) {
        const int n1 = n0 + totalWarps;
        const bool has1 = (n1 < NPTS);

        // ---- prefetch next iteration's labels + indices (hidden by this
        //      iteration's gather+math) ----
        int nxtLab0 = -1, nxtLab1 = -1, nxtIdx = -1;
        const int nn0 = n0 + step;
        if (nn0 < NPTS) {
            nxtLab0 = labels[nn0];
            int nn1 = nn0 + totalWarps;
            nxtLab1 = (nn1 < NPTS) ? labels[nn1] : -1;
            int myPt = (lane < 16) ? nn0 : nn1;
            if (myPt < NPTS) nxtIdx = nbr[myPt * NK + (lane & 15)];
        }

        // ---- own prob rows ----
        __half2 pa0 = z2, pb0 = z2, pa1 = z2, pb1 = z2;
        if (active) {
            uint2 pw0 = *reinterpret_cast<const uint2*>(g_probs_h + n0 * NCLS + laneOff);
            pa0 = *reinterpret_cast<__half2*>(&pw0.x);
            pb0 = *reinterpret_cast<__half2*>(&pw0.y);
            if (has1) {
                uint2 pw1 = *reinterpret_cast<const uint2*>(g_probs_h + n1 * NCLS + laneOff);
                pa1 = *reinterpret_cast<__half2*>(&pw1.x);
                pb1 = *reinterpret_cast<__half2*>(&pw1.y);
            }
        }

        // One ballot covers both points
        unsigned vm = __ballot_sync(0xFFFFFFFFu, curIdx >= 0);
        int nv0 = __popc(vm & 0xFFFFu);
        int nv1 = __popc(vm >> 16);
        bool do0 = (curLab0 != -1) && nv0 > 0;
        bool do1 = has1 && (curLab1 != -1) && nv1 > 0;

        // ---- all 8 shuffles, then all 8 gathers in flight ----
        int q0[4], q1[4];
#pragma unroll
        for (int s = 0; s < 4; s++) {
            q0[s] = __shfl_sync(0xFFFFFFFFu, curIdx, 4 * s + grp);
            q1[s] = __shfl_sync(0xFFFFFFFFu, curIdx, 16 + 4 * s + grp);
        }

        __half2 acc0 = z2, acc1 = z2;
#pragma unroll
        for (int s = 0; s < 4; s++) {
            if (do0 && active && q0[s] >= 0) {
                uint2 qw = *reinterpret_cast<const uint2*>(
                    g_probs_h + q0[s] * NCLS + laneOff);
                __half2 da = __hsub2(pa0, *reinterpret_cast<__half2*>(&qw.x));
                __half2 db = __hsub2(pb0, *reinterpret_cast<__half2*>(&qw.y));
                acc0 = __hfma2(da, da, acc0);
                acc0 = __hfma2(db, db, acc0);
            }
            if (do1 && active && q1[s] >= 0) {
                uint2 qw = *reinterpret_cast<const uint2*>(
                    g_probs_h + q1[s] * NCLS + laneOff);
                __half2 da = __hsub2(pa1, *reinterpret_cast<__half2*>(&qw.x));
                __half2 db = __hsub2(pb1, *reinterpret_cast<__half2*>(&qw.y));
                acc1 = __hfma2(da, da, acc1);
                acc1 = __hfma2(db, db, acc1);
            }
        }

        if (do0) {
            float2 af = __half22float2(acc0);
            accTot = fmaf(af.x + af.y, __frcp_rn((float)nv0), accTot);
        }
        if (do1) {
            float2 af = __half22float2(acc1);
            accTot = fmaf(af.x + af.y, __frcp_rn((float)nv1), accTot);
        }
        cnt += (curLab0 != -1 ? 1.0f : 0.0f) + (has1 && curLab1 != -1 ? 1.0f : 0.0f);

        // rotate prefetch registers
        curLab0 = nxtLab0;
        curLab1 = nxtLab1;
        curIdx  = nxtIdx;
    }

    // One butterfly reduce per warp
#pragma unroll
    for (int o = 16; o > 0; o >>= 1)
        accTot += __shfl_xor_sync(0xFFFFFFFFu, accTot, o);

    // Block reduce -> one atomic pair per block
    __shared__ float sSum[32];
    __shared__ float sCnt[32];
    if (lane == 0) { sSum[warpInBlock] = accTot; sCnt[warpInBlock] = cnt; }
    __syncthreads();
    if (threadIdx.x == 0) {
        float bs = 0.0f, bc = 0.0f;
        for (int w = 0; w < warpsPerBlock; w++) { bs += sSum[w]; bc += sCnt[w]; }
        atomicAdd(&g_acc[0], bs);
        atomicAdd(&g_acc[1], bc);
        __threadfence();
        int t = atomicAdd(&g_done, 1);
        if (t == gridDim.x - 1) {
            out[0] = g_acc[0] / fmaxf(g_acc[1], 1.0f);  // LOSS_WEIGHT = 1.0
            g_done = 0;
        }
    }
}

extern "C" void kernel_launch(void* const* d_in, const int* in_sizes, int n_in,
                              void* d_out, int out_size) {
    const float* logits = nullptr;
    const int*   nbr    = nullptr;
    const int*   labels = nullptr;
    for (int i = 0; i < n_in; i++) {
        if (in_sizes[i] == NPTS * NCLS)    logits = (const float*)d_in[i];
        else if (in_sizes[i] == NPTS * NK) nbr    = (const int*)d_in[i];
        else if (in_sizes[i] == NPTS)      labels = (const int*)d_in[i];
    }
    float* out = (float*)d_out;

    softmax_kernel<<<(NPTS + 255) / 256, 256>>>(logits);
    loss_kernel<<<2048, 256>>>(nbr, labels, out);
}

// round 11
// speedup vs baseline: 1.1177x; 1.0781x over previous
#include <cuda_runtime.h>
#include <cuda_fp16.h>
#include <cstdint>

#define NPTS 500000
#define NCLS 20
#define RPAD 32      // padded row stride in halves (64 B) — passed at runtime as rstride
#define NK   16

// fp16 probs table, 64B rows: 500000*32*2B = 32 MB (L2-resident). No alloc.
__device__ __half g_probs_h[(size_t)NPTS * RPAD];
__device__ float  g_acc[2];    // [0]=sum of mean_dist over valid pts, [1]=valid count
__device__ int    g_done = 0;

// Kernel 1: softmax, smem-staged coalesced loads, padded fp16 rows.
// rstride is a runtime arg so the row-offset multiply stays IMAD (fma pipe).
__global__ void softmax_kernel(const float* __restrict__ logits, int rstride) {
    __shared__ float tile[256 * 21];   // 21-float rows -> conflict-free column reads
    if (blockIdx.x == 0 && threadIdx.x == 0) {
        g_acc[0] = 0.0f;
        g_acc[1] = 0.0f;
        g_done   = 0;
    }
    const int rowBase = blockIdx.x * 256;
    const int rowsInBlock = min(256, NPTS - rowBase);
    if (rowsInBlock <= 0) return;

    // Coalesced float4 tile load: 20 = 5*4, so every float4 lies within one row.
    const float4* s4 = reinterpret_cast<const float4*>(logits + (size_t)rowBase * NCLS);
    const int nvec = rowsInBlock * NCLS / 4;
    for (int i = threadIdx.x; i < nvec; i += 256) {
        float4 v = s4[i];
        int base = i * 4;
        int r = base / NCLS;
        int c = base - r * NCLS;          // in {0,4,8,12,16}
        float* d = &tile[r * 21 + c];
        d[0] = v.x; d[1] = v.y; d[2] = v.z; d[3] = v.w;
    }
    __syncthreads();

    const int n = rowBase + threadIdx.x;
    if (threadIdx.x >= rowsInBlock) return;
    float* f = &tile[threadIdx.x * 21];

    float m = f[0];
#pragma unroll
    for (int i = 1; i < NCLS; i++) m = fmaxf(m, f[i]);
    float s = 0.0f;
    float e[NCLS];
#pragma unroll
    for (int i = 0; i < NCLS; i++) { e[i] = __expf(f[i] - m); s += e[i]; }
    float inv = 1.0f / s;

    __half2 h[10];
#pragma unroll
    for (int i = 0; i < 10; i++)
        h[i] = __floats2half2_rn(e[2 * i] * inv, e[2 * i + 1] * inv);

    // 40B of data at 64B stride: 2x STG.128 + 1x STG.64 (row base 64B-aligned)
    unsigned int* hw = reinterpret_cast<unsigned int*>(h);
    uint4* dst = reinterpret_cast<uint4*>(g_probs_h + (size_t)n * rstride);
    dst[0] = make_uint4(hw[0], hw[1], hw[2], hw[3]);
    dst[1] = make_uint4(hw[4], hw[5], hw[6], hw[7]);
    *reinterpret_cast<uint2*>(dst + 2) = make_uint2(hw[8], hw[9]);
}

// Kernel 2: warp-per-2-points gather (MLP x2), half2 math, line-aligned rows,
// runtime rstride keeps row addressing on the fma pipe (IMAD, not SHF).
// Index layout: lanes 0-15 hold point0's 16 neighbor indices, lanes 16-31 point1's.
// Gather lane layout: grp = lane>>3 (0..3), sub = lane&7; lanes with sub<5 own
// classes [4*sub,4*sub+4) as uint2 (two half2). Step s: group g handles
// neighbor 4*s+g -> one LDG.64 gathers 4 rows, each entirely in one L1 line.
__global__ void loss_kernel(const int* __restrict__ nbr,
                            const int* __restrict__ labels,
                            float* __restrict__ out, int rstride) {
    const int lane = threadIdx.x & 31;
    const int warpInBlock = threadIdx.x >> 5;
    const int warpsPerBlock = blockDim.x >> 5;
    const int gwarp = blockIdx.x * warpsPerBlock + warpInBlock;
    const int totalWarps = gridDim.x * warpsPerBlock;
    const int grp = lane >> 3;
    const int sub = lane & 7;
    const bool active = (sub < 5);
    const int laneOff = 4 * sub;

    float accTot = 0.0f;
    float cnt    = 0.0f;
    const __half2 z2 = __float2half2_rn(0.f);

    for (int n0 = gwarp; n0 < NPTS; n0 += 2 * totalWarps) {
        const int n1 = n0 + totalWarps;
        const bool has1 = (n1 < NPTS);

        int lab0 = labels[n0];
        int lab1 = has1 ? labels[n1] : -1;

        // Full-warp neighbor-index load: lane<16 -> point0, lane>=16 -> point1
        int myPt = (lane < 16) ? n0 : n1;
        int myIdx = -1;
        if (myPt < NPTS) myIdx = nbr[myPt * NK + (lane & 15)];

        __half2 pa0 = z2, pb0 = z2, pa1 = z2, pb1 = z2;
        if (active) {
            uint2 pw0 = *reinterpret_cast<const uint2*>(
                g_probs_h + n0 * rstride + laneOff);
            pa0 = *reinterpret_cast<__half2*>(&pw0.x);
            pb0 = *reinterpret_cast<__half2*>(&pw0.y);
            if (has1) {
                uint2 pw1 = *reinterpret_cast<const uint2*>(
                    g_probs_h + n1 * rstride + laneOff);
                pa1 = *reinterpret_cast<__half2*>(&pw1.x);
                pb1 = *reinterpret_cast<__half2*>(&pw1.y);
            }
        }

        unsigned vm = __ballot_sync(0xFFFFFFFFu, myIdx >= 0);
        int nv0 = __popc(vm & 0xFFFFu);
        int nv1 = __popc(vm >> 16);
        bool do0 = (lab0 != -1) && nv0 > 0;
        bool do1 = has1 && (lab1 != -1) && nv1 > 0;

        int q0[4], q1[4];
#pragma unroll
        for (int s = 0; s < 4; s++) {
            q0[s] = __shfl_sync(0xFFFFFFFFu, myIdx, 4 * s + grp);
            q1[s] = __shfl_sync(0xFFFFFFFFu, myIdx, 16 + 4 * s + grp);
        }

        __half2 acc0 = z2, acc1 = z2;
#pragma unroll
        for (int s = 0; s < 4; s++) {
            if (do0 && active && q0[s] >= 0) {
                uint2 qw = *reinterpret_cast<const uint2*>(
                    g_probs_h + q0[s] * rstride + laneOff);
                __half2 da = __hsub2(pa0, *reinterpret_cast<__half2*>(&qw.x));
                __half2 db = __hsub2(pb0, *reinterpret_cast<__half2*>(&qw.y));
                acc0 = __hfma2(da, da, acc0);
                acc0 = __hfma2(db, db, acc0);
            }
            if (do1 && active && q1[s] >= 0) {
                uint2 qw = *reinterpret_cast<const uint2*>(
                    g_probs_h + q1[s] * rstride + laneOff);
                __half2 da = __hsub2(pa1, *reinterpret_cast<__half2*>(&qw.x));
                __half2 db = __hsub2(pb1, *reinterpret_cast<__half2*>(&qw.y));
                acc1 = __hfma2(da, da, acc1);
                acc1 = __hfma2(db, db, acc1);
            }
        }

        if (do0) {
            float2 af = __half22float2(acc0);
            accTot = fmaf(af.x + af.y, __frcp_rn((float)nv0), accTot);
        }
        if (do1) {
            float2 af = __half22float2(acc1);
            accTot = fmaf(af.x + af.y, __frcp_rn((float)nv1), accTot);
        }
        cnt += (lab0 != -1 ? 1.0f : 0.0f) + (has1 && lab1 != -1 ? 1.0f : 0.0f);
    }

    // One butterfly reduce per warp
#pragma unroll
    for (int o = 16; o > 0; o >>= 1)
        accTot += __shfl_xor_sync(0xFFFFFFFFu, accTot, o);

    // Block reduce -> one atomic pair per block
    __shared__ float sSum[32];
    __shared__ float sCnt[32];
    if (lane == 0) { sSum[warpInBlock] = accTot; sCnt[warpInBlock] = cnt; }
    __syncthreads();
    if (threadIdx.x == 0) {
        float bs = 0.0f, bc = 0.0f;
        for (int w = 0; w < warpsPerBlock; w++) { bs += sSum[w]; bc += sCnt[w]; }
        atomicAdd(&g_acc[0], bs);
        atomicAdd(&g_acc[1], bc);
        __threadfence();
        int t = atomicAdd(&g_done, 1);
        if (t == gridDim.x - 1) {
            out[0] = g_acc[0] / fmaxf(g_acc[1], 1.0f);  // LOSS_WEIGHT = 1.0
            g_done = 0;
        }
    }
}

extern "C" void kernel_launch(void* const* d_in, const int* in_sizes, int n_in,
                              void* d_out, int out_size) {
    const float* logits = nullptr;
    const int*   nbr    = nullptr;
    const int*   labels = nullptr;
    for (int i = 0; i < n_in; i++) {
        if (in_sizes[i] == NPTS * NCLS)    logits = (const float*)d_in[i];
        else if (in_sizes[i] == NPTS * NK) nbr    = (const int*)d_in[i];
        else if (in_sizes[i] == NPTS)      labels = (const int*)d_in[i];
    }
    float* out = (float*)d_out;

    softmax_kernel<<<(NPTS + 255) / 256, 256>>>(logits, RPAD);
    loss_kernel<<<2048, 256>>>(nbr, labels, out, RPAD);
}

// round 12
// speedup vs baseline: 1.2637x; 1.1306x over previous
#include <cuda_runtime.h>
#include <cuda_fp16.h>
#include <cstdint>

#define NPTS 500000
#define NCLS 20
#define RPAD 32      // padded row stride in halves (64 B rows, line-aligned)
#define NK   16

// fp16 probs table, 64B rows: 500000*32*2B = 32 MB (L2-resident). No alloc.
__device__ __half g_probs_h[(size_t)NPTS * RPAD];
__device__ float  g_acc[2];    // [0]=sum of mean_dist over valid pts, [1]=valid count
__device__ int    g_done = 0;

// Kernel 1: softmax, smem-staged coalesced loads, padded fp16 rows.
__global__ void softmax_kernel(const float* __restrict__ logits, int rstride) {
    __shared__ float tile[256 * 21];   // 21-float rows -> conflict-free column reads
    if (blockIdx.x == 0 && threadIdx.x == 0) {
        g_acc[0] = 0.0f;
        g_acc[1] = 0.0f;
        g_done   = 0;
    }
    const int rowBase = blockIdx.x * 256;
    const int rowsInBlock = min(256, NPTS - rowBase);
    if (rowsInBlock <= 0) return;

    // Coalesced float4 tile load: 20 = 5*4, so every float4 lies within one row.
    const float4* s4 = reinterpret_cast<const float4*>(logits + (size_t)rowBase * NCLS);
    const int nvec = rowsInBlock * NCLS / 4;
    for (int i = threadIdx.x; i < nvec; i += 256) {
        float4 v = s4[i];
        int base = i * 4;
        int r = base / NCLS;
        int c = base - r * NCLS;          // in {0,4,8,12,16}
        float* d = &tile[r * 21 + c];
        d[0] = v.x; d[1] = v.y; d[2] = v.z; d[3] = v.w;
    }
    __syncthreads();

    const int n = rowBase + threadIdx.x;
    if (threadIdx.x >= rowsInBlock) return;
    float* f = &tile[threadIdx.x * 21];

    float m = f[0];
#pragma unroll
    for (int i = 1; i < NCLS; i++) m = fmaxf(m, f[i]);
    float s = 0.0f;
    float e[NCLS];
#pragma unroll
    for (int i = 0; i < NCLS; i++) { e[i] = __expf(f[i] - m); s += e[i]; }
    float inv = 1.0f / s;

    __half2 h[10];
#pragma unroll
    for (int i = 0; i < 10; i++)
        h[i] = __floats2half2_rn(e[2 * i] * inv, e[2 * i + 1] * inv);

    // 40B of data at 64B stride: 2x STG.128 + 1x STG.64 (row base 64B-aligned)
    unsigned int* hw = reinterpret_cast<unsigned int*>(h);
    uint4* dst = reinterpret_cast<uint4*>(g_probs_h + (size_t)n * rstride);
    dst[0] = make_uint4(hw[0], hw[1], hw[2], hw[3]);
    dst[1] = make_uint4(hw[4], hw[5], hw[6], hw[7]);
    *reinterpret_cast<uint2*>(dst + 2) = make_uint2(hw[8], hw[9]);
}

// Kernel 2: warp-per-2-points gather (MLP x2), half2 math, line-aligned rows.
// KEY CHANGE vs R11: shuffles carry PRE-MULTIPLIED byte offsets, so each gather
// is laneBase + off (one add) instead of q*stride+laneOff (mul+adds per lane
// per step). One IMAD per index, computed by the index-owning lane only.
// Index layout: lanes 0-15 hold point0's 16 neighbor offsets, lanes 16-31 point1's.
// Gather lane layout: grp = lane>>3 (0..3), sub = lane&7; lanes with sub<5 own
// classes [4*sub,4*sub+4) as uint2 (two half2). Step s: group g handles
// neighbor 4*s+g -> one LDG.64 gathers 4 rows, each entirely in one L1 line.
__global__ void loss_kernel(const int* __restrict__ nbr,
                            const int* __restrict__ labels,
                            float* __restrict__ out, int rstrideB) {
    const int lane = threadIdx.x & 31;
    const int warpInBlock = threadIdx.x >> 5;
    const int warpsPerBlock = blockDim.x >> 5;
    const int gwarp = blockIdx.x * warpsPerBlock + warpInBlock;
    const int totalWarps = gridDim.x * warpsPerBlock;
    const int grp = lane >> 3;
    const int sub = lane & 7;
    const bool active = (sub < 5);
    // Loop-invariant per-lane base: row start + this lane's class-pair offset.
    const char* laneBase = reinterpret_cast<const char*>(g_probs_h) + 8 * sub;

    float accTot = 0.0f;
    float cnt    = 0.0f;
    const __half2 z2 = __float2half2_rn(0.f);

    for (int n0 = gwarp; n0 < NPTS; n0 += 2 * totalWarps) {
        const int n1 = n0 + totalWarps;
        const bool has1 = (n1 < NPTS);

        int lab0 = labels[n0];
        int lab1 = has1 ? labels[n1] : -1;

        // Full-warp neighbor-index load, pre-multiplied to a byte offset.
        int myPt = (lane < 16) ? n0 : n1;
        int myOff = -1;
        if (myPt < NPTS) myOff = nbr[myPt * NK + (lane & 15)] * rstrideB; // keeps sign
        unsigned vm = __ballot_sync(0xFFFFFFFFu, myOff >= 0);
        int nv0 = __popc(vm & 0xFFFFu);
        int nv1 = __popc(vm >> 16);
        bool do0 = (lab0 != -1) && nv0 > 0;
        bool do1 = has1 && (lab1 != -1) && nv1 > 0;

        // Own prob rows via the same offset form
        __half2 pa0 = z2, pb0 = z2, pa1 = z2, pb1 = z2;
        if (active) {
            uint2 pw0 = *reinterpret_cast<const uint2*>(laneBase + n0 * rstrideB);
            pa0 = *reinterpret_cast<const __half2*>(&pw0.x);
            pb0 = *reinterpret_cast<const __half2*>(&pw0.y);
            if (has1) {
                uint2 pw1 = *reinterpret_cast<const uint2*>(laneBase + n1 * rstrideB);
                pa1 = *reinterpret_cast<const __half2*>(&pw1.x);
                pb1 = *reinterpret_cast<const __half2*>(&pw1.y);
            }
        }

        // Shuffle ready-made byte offsets; all 8 gathers in flight.
        int q0[4], q1[4];
#pragma unroll
        for (int s = 0; s < 4; s++) {
            q0[s] = __shfl_sync(0xFFFFFFFFu, myOff, 4 * s + grp);
            q1[s] = __shfl_sync(0xFFFFFFFFu, myOff, 16 + 4 * s + grp);
        }

        __half2 acc0 = z2, acc1 = z2;
#pragma unroll
        for (int s = 0; s < 4; s++) {
            if (do0 && active && q0[s] >= 0) {
                uint2 qw = *reinterpret_cast<const uint2*>(laneBase + q0[s]);
                __half2 da = __hsub2(pa0, *reinterpret_cast<const __half2*>(&qw.x));
                __half2 db = __hsub2(pb0, *reinterpret_cast<const __half2*>(&qw.y));
                acc0 = __hfma2(da, da, acc0);
                acc0 = __hfma2(db, db, acc0);
            }
            if (do1 && active && q1[s] >= 0) {
                uint2 qw = *reinterpret_cast<const uint2*>(laneBase + q1[s]);
                __half2 da = __hsub2(pa1, *reinterpret_cast<const __half2*>(&qw.x));
                __half2 db = __hsub2(pb1, *reinterpret_cast<const __half2*>(&qw.y));
                acc1 = __hfma2(da, da, acc1);
                acc1 = __hfma2(db, db, acc1);
            }
        }

        if (do0) {
            float2 af = __half22float2(acc0);
            accTot = fmaf(af.x + af.y, __frcp_rn((float)nv0), accTot);
        }
        if (do1) {
            float2 af = __half22float2(acc1);
            accTot = fmaf(af.x + af.y, __frcp_rn((float)nv1), accTot);
        }
        cnt += (lab0 != -1 ? 1.0f : 0.0f) + (has1 && lab1 != -1 ? 1.0f : 0.0f);
    }

    // One butterfly reduce per warp
#pragma unroll
    for (int o = 16; o > 0; o >>= 1)
        accTot += __shfl_xor_sync(0xFFFFFFFFu, accTot, o);

    // Block reduce -> one atomic pair per block
    __shared__ float sSum[32];
    __shared__ float sCnt[32];
    if (lane == 0) { sSum[warpInBlock] = accTot; sCnt[warpInBlock] = cnt; }
    __syncthreads();
    if (threadIdx.x == 0) {
        float bs = 0.0f, bc = 0.0f;
        for (int w = 0; w < warpsPerBlock; w++) { bs += sSum[w]; bc += sCnt[w]; }
        atomicAdd(&g_acc[0], bs);
        atomicAdd(&g_acc[1], bc);
        __threadfence();
        int t = atomicAdd(&g_done, 1);
        if (t == gridDim.x - 1) {
            out[0] = g_acc[0] / fmaxf(g_acc[1], 1.0f);  // LOSS_WEIGHT = 1.0
            g_done = 0;
        }
    }
}

extern "C" void kernel_launch(void* const* d_in, const int* in_sizes, int n_in,
                              void* d_out, int out_size) {
    const float* logits = nullptr;
    const int*   nbr    = nullptr;
    const int*   labels = nullptr;
    for (int i = 0; i < n_in; i++) {
        if (in_sizes[i] == NPTS * NCLS)    logits = (const float*)d_in[i];
        else if (in_sizes[i] == NPTS * NK) nbr    = (const int*)d_in[i];
        else if (in_sizes[i] == NPTS)      labels = (const int*)d_in[i];
    }
    float* out = (float*)d_out;

    softmax_kernel<<<(NPTS + 255) / 256, 256>>>(logits, RPAD);
    loss_kernel<<<2048, 256>>>(nbr, labels, out, RPAD * 2 /* bytes per row */);
}